// round 9
// baseline (speedup 1.0000x reference)
#include <cuda_runtime.h>
#include <cuda_bf16.h>
#include <math.h>
#include <stdint.h>

// ---------------- problem constants ----------------
#define NB     8
#define CIN    256
#define HH     128
#define WW     128
#define HWD    16384            // HH*WW
#define NHW    131072           // NB*HWD
#define C2     128
#define GR     8
#define C2G    16               // C2/GR
#define SH     64               // sp spatial
#define SHW    4096             // 64*64

// ---------------- scratch (device globals; no allocs allowed) ----------------
__device__ float g_sp_t[NB * SHW * CIN];        //  8.4M  sp  NHWC
__device__ float g_cp_t[NB * HWD * CIN];        // 33.6M  cp  NHWC
__device__ float g_spup_t[NB * HWD * CIN];      // 33.6M  sp_up NHWC
__device__ float g_cp1[NB * C2 * HWD];          // 16.8M  NCHW
__device__ float g_sp1[NB * C2 * HWD];          // 16.8M
__device__ float g_redim[NB * C2 * HWD];        // 16.8M
__device__ float g_sim[NB * GR * HWD];          //  1.0M
__device__ float g_fdif[NB * C2 * HWD];         // 16.8M
__device__ float g_fdir[NB * 32 * HWD];         //  4.2M
__device__ float g_fdist[NB * 32 * HWD];        //  4.2M
__device__ float g_wofft[192 * 32];             // w_off transposed [ci][co]

// split 8 f32 -> bf16 hi/lo packed pairs
__device__ __forceinline__ void split8(const float* v, uint4& H, uint4& L) {
    unsigned h[8], l[8];
    #pragma unroll
    for (int j = 0; j < 8; j++) {
        __nv_bfloat16 hb = __float2bfloat16(v[j]);
        float r = v[j] - __bfloat162float(hb);
        __nv_bfloat16 lb = __float2bfloat16(r);
        h[j] = (unsigned)__bfloat16_as_ushort(hb);
        l[j] = (unsigned)__bfloat16_as_ushort(lb);
    }
    H = make_uint4(h[0] | (h[1] << 16), h[2] | (h[3] << 16),
                   h[4] | (h[5] << 16), h[6] | (h[7] << 16));
    L = make_uint4(l[0] | (l[1] << 16), l[2] | (l[3] << 16),
                   l[4] | (l[5] << 16), l[6] | (l[7] << 16));
}

#define MMA16816(C, A, B) \
    asm volatile( \
        "mma.sync.aligned.m16n8k16.row.col.f32.bf16.bf16.f32 " \
        "{%0,%1,%2,%3}, {%4,%5,%6,%7}, {%8,%9}, {%0,%1,%2,%3};" \
        : "+f"((C)[0]), "+f"((C)[1]), "+f"((C)[2]), "+f"((C)[3]) \
        : "r"((A)[0]), "r"((A)[1]), "r"((A)[2]), "r"((A)[3]), \
          "r"((B)[0]), "r"((B)[1]))

// ================ tensor-core 1x1 conv via mma.sync bf16 hi/lo split ================
// out[co,px] = sum_ci W[co,ci]*X[ci,px]; CO=128, CI=256; CTA tile 128co x 64px.
// 8 warps: warp w -> rows (w&3)*32..+32, cols (w>>2)*32..+32 (2x4 m16n8k16 frags).
// smem rows stride 40 halfwords (80B) for 16B-aligned stores.
#define AST 40
__global__ __launch_bounds__(256)
void conv1x1_mma_kernel(const float* __restrict__ in0, const float* __restrict__ in1,
                        int ci0, int nhwc, const float* __restrict__ Wt,
                        const float* __restrict__ gamma, const float* __restrict__ beta,
                        int relu, float* __restrict__ out) {
    __shared__ __align__(16) unsigned char smraw[33792];
    __nv_bfloat16* Ah = (__nv_bfloat16*)smraw;              // [128][40]
    __nv_bfloat16* Al = (__nv_bfloat16*)(smraw + 10240);
    __nv_bfloat16* Bh = (__nv_bfloat16*)(smraw + 20480);    // [64][40]
    __nv_bfloat16* Bl = (__nv_bfloat16*)(smraw + 25600);

    int t = threadIdx.x, lane = t & 31, w = t >> 5;
    int qb = blockIdx.x * 64;
    int n = qb >> 14, hwb = qb & (HWD - 1);
    int wco = (w & 3) * 32, wpx = (w >> 2) * 32;
    int g = lane >> 2, t2 = (lane & 3) * 2;

    float acc[2][4][4];
    #pragma unroll
    for (int a = 0; a < 2; a++)
        #pragma unroll
        for (int b = 0; b < 4; b++)
            #pragma unroll
            for (int c = 0; c < 4; c++) acc[a][b][c] = 0.f;

    int a_co = t >> 1, a_k = (t & 1) * 16;        // A loader: 16 floats/thread
    int b_px = t & 63, b_kg = t >> 6;             // B nchw: 8 floats/thread
    int c_px = t >> 2, c_k8 = (t & 3) * 8;        // B nhwc

    for (int ch = 0; ch < 8; ch++) {
        int kb = ch * 32;
        // ---- A tile: W[co][kb..kb+32) ----
        {
            const float* srcw = Wt + (size_t)a_co * 256 + kb + a_k;
            float v[8];
            float4 f0 = *(const float4*)srcw, f1 = *(const float4*)(srcw + 4);
            v[0]=f0.x; v[1]=f0.y; v[2]=f0.z; v[3]=f0.w; v[4]=f1.x; v[5]=f1.y; v[6]=f1.z; v[7]=f1.w;
            uint4 H, L; split8(v, H, L);
            *(uint4*)&Ah[a_co * AST + a_k]     = H;
            *(uint4*)&Al[a_co * AST + a_k]     = L;
            f0 = *(const float4*)(srcw + 8); f1 = *(const float4*)(srcw + 12);
            v[0]=f0.x; v[1]=f0.y; v[2]=f0.z; v[3]=f0.w; v[4]=f1.x; v[5]=f1.y; v[6]=f1.z; v[7]=f1.w;
            split8(v, H, L);
            *(uint4*)&Ah[a_co * AST + a_k + 8] = H;
            *(uint4*)&Al[a_co * AST + a_k + 8] = L;
        }
        // ---- B tile: X[px][kb..kb+32) ----
        if (!nhwc) {
            float v[8];
            #pragma unroll
            for (int j = 0; j < 8; j++) {
                int ci = kb + b_kg * 8 + j;
                const float* s2 = (ci < ci0)
                    ? &in0[(size_t)((n * ci0 + ci) << 14) + hwb + b_px]
                    : &in1[(size_t)((n * (256 - ci0) + (ci - ci0)) << 14) + hwb + b_px];
                v[j] = *s2;
            }
            uint4 H, L; split8(v, H, L);
            *(uint4*)&Bh[b_px * AST + b_kg * 8] = H;
            *(uint4*)&Bl[b_px * AST + b_kg * 8] = L;
        } else {
            const float* s2 = &in0[((size_t)(n << 14) + hwb + c_px) * 256 + kb + c_k8];
            float v[8];
            float4 f0 = *(const float4*)s2, f1 = *(const float4*)(s2 + 4);
            v[0]=f0.x; v[1]=f0.y; v[2]=f0.z; v[3]=f0.w; v[4]=f1.x; v[5]=f1.y; v[6]=f1.z; v[7]=f1.w;
            uint4 H, L; split8(v, H, L);
            *(uint4*)&Bh[c_px * AST + c_k8] = H;
            *(uint4*)&Bl[c_px * AST + c_k8] = L;
        }
        __syncthreads();
        // ---- 2 k16-steps of HMMA ----
        #pragma unroll
        for (int ks = 0; ks < 2; ks++) {
            int khw = ks * 16;
            unsigned ah[2][4], al[2][4], bh[4][2], bl[4][2];
            #pragma unroll
            for (int mi = 0; mi < 2; mi++) {
                int r0 = (wco + mi * 16 + g) * AST + khw + t2;
                int r1 = r0 + 8 * AST;
                ah[mi][0] = *(unsigned*)&Ah[r0];     ah[mi][1] = *(unsigned*)&Ah[r1];
                ah[mi][2] = *(unsigned*)&Ah[r0 + 8]; ah[mi][3] = *(unsigned*)&Ah[r1 + 8];
                al[mi][0] = *(unsigned*)&Al[r0];     al[mi][1] = *(unsigned*)&Al[r1];
                al[mi][2] = *(unsigned*)&Al[r0 + 8]; al[mi][3] = *(unsigned*)&Al[r1 + 8];
            }
            #pragma unroll
            for (int nj = 0; nj < 4; nj++) {
                int p0 = (wpx + nj * 8 + g) * AST + khw + t2;
                bh[nj][0] = *(unsigned*)&Bh[p0]; bh[nj][1] = *(unsigned*)&Bh[p0 + 8];
                bl[nj][0] = *(unsigned*)&Bl[p0]; bl[nj][1] = *(unsigned*)&Bl[p0 + 8];
            }
            #pragma unroll
            for (int mi = 0; mi < 2; mi++)
                #pragma unroll
                for (int nj = 0; nj < 4; nj++) {
                    MMA16816(acc[mi][nj], ah[mi], bh[nj]);
                    MMA16816(acc[mi][nj], ah[mi], bl[nj]);
                    MMA16816(acc[mi][nj], al[mi], bh[nj]);
                }
        }
        __syncthreads();
    }

    // ---- epilogue: BN/ReLU or +bias, stage via smem for coalesced NCHW stores ----
    float* tile = (float*)smraw;                // [128][66]
    const float rs = rsqrtf(1.0f + 1e-5f);
    #pragma unroll
    for (int mi = 0; mi < 2; mi++) {
        int ra = wco + mi * 16 + g, rb = ra + 8;
        float sa = 1.f, ba, sb2 = 1.f, bb;
        if (gamma) { sa = __ldg(&gamma[ra]) * rs; ba = __ldg(&beta[ra]);
                     sb2 = __ldg(&gamma[rb]) * rs; bb = __ldg(&beta[rb]); }
        else { ba = __ldg(&beta[ra]); bb = __ldg(&beta[rb]); }
        #pragma unroll
        for (int nj = 0; nj < 4; nj++) {
            int px = wpx + nj * 8 + t2;
            float v0 = acc[mi][nj][0], v1 = acc[mi][nj][1];
            float v2 = acc[mi][nj][2], v3 = acc[mi][nj][3];
            if (gamma) {
                v0 = fmaf(v0, sa, ba);  v1 = fmaf(v1, sa, ba);
                v2 = fmaf(v2, sb2, bb); v3 = fmaf(v3, sb2, bb);
                if (relu) { v0 = fmaxf(v0, 0.f); v1 = fmaxf(v1, 0.f);
                            v2 = fmaxf(v2, 0.f); v3 = fmaxf(v3, 0.f); }
            } else { v0 += ba; v1 += ba; v2 += bb; v3 += bb; }
            tile[ra * 66 + px] = v0; tile[ra * 66 + px + 1] = v1;
            tile[rb * 66 + px] = v2; tile[rb * 66 + px + 1] = v3;
        }
    }
    __syncthreads();
    for (int i = t; i < 8192; i += 256) {
        int cc = i >> 6, px = i & 63;
        out[(size_t)((n * 128 + cc) << 14) + hwb + px] = tile[cc * 66 + px];
    }
}

// ---------------- transpose NCHW -> NHWC ----------------
__global__ void transpose_kernel(const float* __restrict__ in, float* __restrict__ out,
                                 int C, int HW) {
    __shared__ float tile[32][33];
    int hwb = blockIdx.x * 32, cb = blockIdx.y * 32, n = blockIdx.z;
    int lane = threadIdx.x & 31, row = threadIdx.x >> 5;
    #pragma unroll
    for (int r = row; r < 32; r += 8)
        tile[r][lane] = in[(size_t)(n * C + cb + r) * HW + hwb + lane];
    __syncthreads();
    #pragma unroll
    for (int r = row; r < 32; r += 8)
        out[((size_t)n * HW + hwb + r) * C + cb + lane] = tile[lane][r];
}

// ---------------- transpose w_off [32][192] -> [192][32] ----------------
__global__ void woff_transpose_kernel(const float* __restrict__ w, float* __restrict__ wt) {
    int i = blockIdx.x * 256 + threadIdx.x;
    if (i < 32 * 192) {
        int co = i / 192, ci = i - co * 192;
        wt[ci * 32 + co] = w[i];
    }
}

// ---------------- bilinear upsample (align_corners) in NHWC ----------------
__global__ void upsample_kernel(const float* __restrict__ sp_t, float* __restrict__ out_t) {
    int idx = blockIdx.x * 256 + threadIdx.x;
    int c4 = idx & 63;
    int p  = idx >> 6;
    int hw = p & (HWD - 1);
    int n  = p >> 14;
    int oy = hw >> 7, ox = hw & 127;
    float sy = oy * (63.0f / 127.0f);
    float sx = ox * (63.0f / 127.0f);
    int y0 = (int)sy; float wy = sy - (float)y0; int y1 = min(y0 + 1, 63);
    int x0 = (int)sx; float wx = sx - (float)x0; int x1 = min(x0 + 1, 63);
    const float4* s = (const float4*)sp_t;
    size_t b = (size_t)n * SHW;
    float4 v00 = s[(b + y0 * 64 + x0) * 64 + c4];
    float4 v01 = s[(b + y0 * 64 + x1) * 64 + c4];
    float4 v10 = s[(b + y1 * 64 + x0) * 64 + c4];
    float4 v11 = s[(b + y1 * 64 + x1) * 64 + c4];
    float w00 = (1.f - wy) * (1.f - wx), w01 = (1.f - wy) * wx;
    float w10 = wy * (1.f - wx),         w11 = wy * wx;
    float4 r;
    r.x = v00.x * w00 + v01.x * w01 + v10.x * w10 + v11.x * w11;
    r.y = v00.y * w00 + v01.y * w01 + v10.y * w10 + v11.y * w11;
    r.z = v00.z * w00 + v01.z * w01 + v10.z * w10 + v11.z * w11;
    r.w = v00.w * w00 + v01.w * w01 + v10.w * w10 + v11.w * w11;
    ((float4*)out_t)[(size_t)p * 64 + c4] = r;
}

// ---------------- grouped cosine sim + |cp1-sp1| ----------------
__global__ void simfdif_kernel(const float* __restrict__ cp1, const float* __restrict__ sp1,
                               float* __restrict__ fdif, float* __restrict__ sim) {
    int idx = blockIdx.x * 256 + threadIdx.x;
    int hw = idx & (HWD - 1);
    int ng = idx >> 14;
    int gi = ng & 7, n = ng >> 3;
    size_t base = (size_t)((n * C2 + gi * C2G) << 14) + hw;
    float num = 0.f, na = 0.f, nb = 0.f;
    #pragma unroll
    for (int c = 0; c < C2G; c++) {
        float a = cp1[base + ((size_t)c << 14)];
        float b = sp1[base + ((size_t)c << 14)];
        num += a * b; na += a * a; nb += b * b;
        fdif[base + ((size_t)c << 14)] = fabsf(a - b);
    }
    sim[((size_t)ng << 14) + hw] =
        num / (fmaxf(sqrtf(na), 1e-8f) * fmaxf(sqrtf(nb), 1e-8f));
}

// ---------------- 3x3 conv, pad 1, CO=32 ----------------
__global__ void conv3x3_kernel(const float* __restrict__ in, const float* __restrict__ wgt,
                               const float* __restrict__ bias, float* __restrict__ out, int CI) {
    __shared__ float ps[4][10][36];
    __shared__ __align__(16) float ws[4][9][32];
    int t  = threadIdx.x;
    int o  = t >> 6;
    int q  = t & 63;
    int ty = q >> 3;
    int tx = (q & 7) * 4;
    int n  = blockIdx.z;
    int y0 = blockIdx.y * 8, x0 = blockIdx.x * 32;
    float acc[8][4];
    #pragma unroll
    for (int a = 0; a < 8; a++)
        #pragma unroll
        for (int b = 0; b < 4; b++) acc[a][b] = 0.f;

    for (int cb = 0; cb < CI; cb += 4) {
        __syncthreads();
        for (int i = t; i < 4 * 10 * 34; i += 256) {
            int cc = i / 340; int rem = i - cc * 340;
            int yy = rem / 34; int xx = rem - yy * 34;
            int gy = y0 + yy - 1, gx = x0 + xx - 1;
            float v = 0.f;
            if (gy >= 0 && gy < HH && gx >= 0 && gx < WW)
                v = in[(size_t)((n * CI + cb + cc) << 14) + (gy << 7) + gx];
            ps[cc][yy][xx] = v;
        }
        for (int i = t; i < 4 * 32 * 9; i += 256) {
            int cc = i / 288; int rem = i - cc * 288;
            int tap = rem >> 5; int co = rem & 31;
            ws[cc][tap][co] = wgt[(size_t)(co * CI + cb + cc) * 9 + tap];
        }
        __syncthreads();
        #pragma unroll
        for (int cc = 0; cc < 4; cc++) {
            float p[3][6];
            #pragma unroll
            for (int yy = 0; yy < 3; yy++)
                #pragma unroll
                for (int xx = 0; xx < 6; xx++)
                    p[yy][xx] = ps[cc][ty + yy][tx + xx];
            #pragma unroll
            for (int tap = 0; tap < 9; tap++) {
                int ky = tap / 3, kx = tap - ky * 3;
                float4 w0 = *(const float4*)&ws[cc][tap][o * 8];
                float4 w1 = *(const float4*)&ws[cc][tap][o * 8 + 4];
                float wv[8] = {w0.x, w0.y, w0.z, w0.w, w1.x, w1.y, w1.z, w1.w};
                #pragma unroll
                for (int c8 = 0; c8 < 8; c8++) {
                    acc[c8][0] += wv[c8] * p[ky][kx + 0];
                    acc[c8][1] += wv[c8] * p[ky][kx + 1];
                    acc[c8][2] += wv[c8] * p[ky][kx + 2];
                    acc[c8][3] += wv[c8] * p[ky][kx + 3];
                }
            }
        }
    }
    #pragma unroll
    for (int c8 = 0; c8 < 8; c8++) {
        int co = o * 8 + c8;
        float b = bias[co];
        size_t ob = (size_t)((n * 32 + co) << 14) + ((y0 + ty) << 7) + x0 + tx;
        #pragma unroll
        for (int j = 0; j < 4; j++) out[ob + j] = acc[c8][j] + b;
    }
}

// ---------------- fused off 1x1 conv + dual grid_sample ----------------
__device__ __forceinline__ float4 sample32(const float* __restrict__ src_t, int n,
                                           int chan4, float gx, float gy) {
    float x0f = floorf(gx), y0f = floorf(gy);
    int x0 = (int)x0f, y0 = (int)y0f;
    float wx = gx - x0f, wy = gy - y0f;
    bool vx0 = (x0 >= 0) & (x0 <= WW - 1);
    bool vx1 = (x0 + 1 >= 0) & (x0 + 1 <= WW - 1);
    bool vy0 = (y0 >= 0) & (y0 <= HH - 1);
    bool vy1 = (y0 + 1 >= 0) & (y0 + 1 <= HH - 1);
    float c00 = (vx0 && vy0) ? (1.f - wx) * (1.f - wy) : 0.f;
    float c01 = (vx1 && vy0) ? wx * (1.f - wy) : 0.f;
    float c10 = (vx0 && vy1) ? (1.f - wx) * wy : 0.f;
    float c11 = (vx1 && vy1) ? wx * wy : 0.f;
    int xc0 = min(max(x0, 0), WW - 1), xc1 = min(max(x0 + 1, 0), WW - 1);
    int yc0 = min(max(y0, 0), HH - 1), yc1 = min(max(y0 + 1, 0), HH - 1);
    const float4* p = (const float4*)src_t;
    size_t b = (size_t)(n << 14);
    float4 v00 = p[(b + (yc0 << 7) + xc0) * 64 + chan4];
    float4 v01 = p[(b + (yc0 << 7) + xc1) * 64 + chan4];
    float4 v10 = p[(b + (yc1 << 7) + xc0) * 64 + chan4];
    float4 v11 = p[(b + (yc1 << 7) + xc1) * 64 + chan4];
    float4 r;
    r.x = v00.x * c00 + v01.x * c01 + v10.x * c10 + v11.x * c11;
    r.y = v00.y * c00 + v01.y * c01 + v10.y * c10 + v11.y * c11;
    r.z = v00.z * c00 + v01.z * c01 + v10.z * c10 + v11.z * c11;
    r.w = v00.w * c00 + v01.w * c01 + v10.w * c10 + v11.w * c11;
    return r;
}

__global__ void offgrid_kernel(const float* __restrict__ redim, const float* __restrict__ fdir,
                               const float* __restrict__ fdist, const float* __restrict__ Wofft,
                               const float* __restrict__ boff, const float* __restrict__ cp_t,
                               const float* __restrict__ spup_t, float* __restrict__ out) {
    __shared__ float buf[256 * 32];
    __shared__ float off_s[32][33];
    int t   = threadIdx.x;
    int qb  = blockIdx.x * 32;
    int n   = qb >> 14;
    int hwb = qb & (HWD - 1);
    int lane = t & 31, wid = t >> 5;

    for (int i = t; i < 192 * 32; i += 256) {
        int ci = i >> 5; int px = i & 31; int hw = hwb + px;
        float v;
        if (ci < 128)      v = redim[(size_t)((n * C2 + ci) << 14) + hw];
        else if (ci < 160) v = fdir[(size_t)((n * 32 + ci - 128) << 14) + hw];
        else               v = fdist[(size_t)((n * 32 + ci - 160) << 14) + hw];
        buf[i] = v;
    }
    __syncthreads();
    {
        float a0 = 0.f, a1 = 0.f, a2 = 0.f, a3 = 0.f;
        const float4* wt = (const float4*)Wofft;
        #pragma unroll 4
        for (int ci = 0; ci < 192; ci++) {
            float4 wv = __ldg(&wt[ci * 8 + wid]);
            float x = buf[ci * 32 + lane];
            a0 += wv.x * x; a1 += wv.y * x; a2 += wv.z * x; a3 += wv.w * x;
        }
        off_s[lane][wid * 4 + 0] = a0 + __ldg(&boff[wid * 4 + 0]);
        off_s[lane][wid * 4 + 1] = a1 + __ldg(&boff[wid * 4 + 1]);
        off_s[lane][wid * 4 + 2] = a2 + __ldg(&boff[wid * 4 + 2]);
        off_s[lane][wid * 4 + 3] = a3 + __ldg(&boff[wid * 4 + 3]);
    }
    __syncthreads();

    int gi = wid;
    int cc4  = lane & 7; int sub = lane >> 3;
    const float K = 127.0f / 256.0f;
    for (int it = 0; it < 8; it++) {
        int px = it * 4 + sub;
        int hw = hwb + px;
        int ox = hw & 127, oy = hw >> 7;
        float olx = off_s[px][2 * gi],      oly = off_s[px][2 * gi + 1];
        float ohx = off_s[px][16 + 2 * gi], ohy = off_s[px][16 + 2 * gi + 1];
        int chan4 = gi * 8 + cc4;
        float4 a = sample32(cp_t,   n, chan4, (float)ox + olx * K, (float)oy + oly * K);
        float4 b = sample32(spup_t, n, chan4, (float)ox + ohx * K, (float)oy + ohy * K);
        int cbase = (gi * 32 + cc4 * 4) * 32 + px;
        buf[cbase + 0]  = a.x + b.x;
        buf[cbase + 32] = a.y + b.y;
        buf[cbase + 64] = a.z + b.z;
        buf[cbase + 96] = a.w + b.w;
    }
    __syncthreads();
    for (int i = t; i < 256 * 32; i += 256) {
        int c = i >> 5; int px = i & 31;
        out[(size_t)((n * 256 + c) << 14) + hwb + px] = buf[i];
    }
}

// ---------------- launch ----------------
extern "C" void kernel_launch(void* const* d_in, const int* in_sizes, int n_in,
                              void* d_out, int out_size) {
    const float* cp      = (const float*)d_in[0];
    const float* sp      = (const float*)d_in[1];
    const float* w_cp    = (const float*)d_in[2];
    const float* gm_cp   = (const float*)d_in[3];
    const float* b_cp    = (const float*)d_in[4];
    const float* w_sp    = (const float*)d_in[5];
    const float* gm_sp   = (const float*)d_in[6];
    const float* b_sp    = (const float*)d_in[7];
    const float* w_redim = (const float*)d_in[8];
    const float* b_redim = (const float*)d_in[9];
    const float* w_dir   = (const float*)d_in[10];
    const float* b_dir   = (const float*)d_in[11];
    const float* w_dist  = (const float*)d_in[12];
    const float* b_dist  = (const float*)d_in[13];
    const float* w_off   = (const float*)d_in[14];
    const float* b_off   = (const float*)d_in[15];
    float* out = (float*)d_out;

    float* sp_t   = nullptr; cudaGetSymbolAddress((void**)&sp_t,   g_sp_t);
    float* cp_t   = nullptr; cudaGetSymbolAddress((void**)&cp_t,   g_cp_t);
    float* spup_t = nullptr; cudaGetSymbolAddress((void**)&spup_t, g_spup_t);
    float* cp1    = nullptr; cudaGetSymbolAddress((void**)&cp1,    g_cp1);
    float* sp1    = nullptr; cudaGetSymbolAddress((void**)&sp1,    g_sp1);
    float* redim  = nullptr; cudaGetSymbolAddress((void**)&redim,  g_redim);
    float* sim    = nullptr; cudaGetSymbolAddress((void**)&sim,    g_sim);
    float* fdif   = nullptr; cudaGetSymbolAddress((void**)&fdif,   g_fdif);
    float* fdir   = nullptr; cudaGetSymbolAddress((void**)&fdir,   g_fdir);
    float* fdist  = nullptr; cudaGetSymbolAddress((void**)&fdist,  g_fdist);
    float* wofft  = nullptr; cudaGetSymbolAddress((void**)&wofft,  g_wofft);

    transpose_kernel<<<dim3(HWD / 32, CIN / 32, NB), 256>>>(cp, cp_t, CIN, HWD);
    transpose_kernel<<<dim3(SHW / 32, CIN / 32, NB), 256>>>(sp, sp_t, CIN, SHW);
    woff_transpose_kernel<<<24, 256>>>(w_off, wofft);
    upsample_kernel<<<(NB * HWD * 64) / 256, 256>>>(sp_t, spup_t);
    // cp1 = bn_relu(conv1x1(cp))          [NCHW in]
    conv1x1_mma_kernel<<<NHW / 64, 256>>>(cp, nullptr, 256, 0, w_cp, gm_cp, b_cp, 1, cp1);
    // sp1 = bn_relu(conv1x1(sp_up))       [NHWC in]
    conv1x1_mma_kernel<<<NHW / 64, 256>>>(spup_t, nullptr, 256, 1, w_sp, gm_sp, b_sp, 1, sp1);
    // redim = conv1x1(concat(cp1, sp1)) + b
    conv1x1_mma_kernel<<<NHW / 64, 256>>>(cp1, sp1, 128, 0, w_redim, nullptr, b_redim, 0, redim);
    simfdif_kernel<<<(NB * GR * HWD) / 256, 256>>>(cp1, sp1, fdif, sim);
    conv3x3_kernel<<<dim3(WW / 32, HH / 8, NB), 256>>>(sim, w_dir, b_dir, fdir, GR);
    conv3x3_kernel<<<dim3(WW / 32, HH / 8, NB), 256>>>(fdif, w_dist, b_dist, fdist, C2);
    offgrid_kernel<<<NHW / 32, 256>>>(redim, fdir, fdist, wofft, b_off, cp_t, spup_t, out);
}

// round 11
// speedup vs baseline: 1.2205x; 1.2205x over previous
#include <cuda_runtime.h>
#include <math.h>

// ---------------- problem constants ----------------
#define NB     8
#define CIN    256
#define HH     128
#define WW     128
#define HWD    16384            // HH*WW
#define NHW    131072           // NB*HWD
#define C2     128
#define GR     8
#define C2G    16               // C2/GR
#define SH     64               // sp spatial
#define SHW    4096             // 64*64

// ---------------- scratch (device globals; no allocs allowed) ----------------
__device__ float g_sp_t[NB * SHW * CIN];        //  8.4M  sp  NHWC
__device__ float g_cp_t[NB * HWD * CIN];        // 33.6M  cp  NHWC
__device__ float g_spup_t[NB * HWD * CIN];      // 33.6M  sp_up NHWC
__device__ float g_cp1[NB * C2 * HWD];          // 16.8M  NCHW
__device__ float g_sp1[NB * C2 * HWD];          // 16.8M
__device__ float g_redim[NB * C2 * HWD];        // 16.8M
__device__ float g_sim[NB * GR * HWD];          //  1.0M
__device__ float g_fdif[NB * C2 * HWD];         // 16.8M
__device__ float g_fdir[NB * 32 * HWD];         //  4.2M
__device__ float g_fdist[NB * 32 * HWD];        //  4.2M
__device__ float g_wofft[192 * 32];             // w_off transposed [ci][co]

// ---------------- transpose NCHW -> NHWC ----------------
__global__ void transpose_kernel(const float* __restrict__ in, float* __restrict__ out,
                                 int C, int HW) {
    __shared__ float tile[32][33];
    int hwb = blockIdx.x * 32, cb = blockIdx.y * 32, n = blockIdx.z;
    int lane = threadIdx.x & 31, row = threadIdx.x >> 5;
    #pragma unroll
    for (int r = row; r < 32; r += 8)
        tile[r][lane] = in[(size_t)(n * C + cb + r) * HW + hwb + lane];
    __syncthreads();
    #pragma unroll
    for (int r = row; r < 32; r += 8)
        out[((size_t)n * HW + hwb + r) * C + cb + lane] = tile[lane][r];
}

// ---------------- transpose w_off [32][192] -> [192][32] ----------------
__global__ void woff_transpose_kernel(const float* __restrict__ w, float* __restrict__ wt) {
    int i = blockIdx.x * 256 + threadIdx.x;
    if (i < 32 * 192) {
        int co = i / 192, ci = i - co * 192;
        wt[ci * 32 + co] = w[i];
    }
}

// ---------------- bilinear upsample (align_corners) in NHWC ----------------
__global__ void upsample_kernel(const float* __restrict__ sp_t, float* __restrict__ out_t) {
    int idx = blockIdx.x * 256 + threadIdx.x;
    int c4 = idx & 63;
    int p  = idx >> 6;
    int hw = p & (HWD - 1);
    int n  = p >> 14;
    int oy = hw >> 7, ox = hw & 127;
    float sy = oy * (63.0f / 127.0f);
    float sx = ox * (63.0f / 127.0f);
    int y0 = (int)sy; float wy = sy - (float)y0; int y1 = min(y0 + 1, 63);
    int x0 = (int)sx; float wx = sx - (float)x0; int x1 = min(x0 + 1, 63);
    const float4* s = (const float4*)sp_t;
    size_t b = (size_t)n * SHW;
    float4 v00 = s[(b + y0 * 64 + x0) * 64 + c4];
    float4 v01 = s[(b + y0 * 64 + x1) * 64 + c4];
    float4 v10 = s[(b + y1 * 64 + x0) * 64 + c4];
    float4 v11 = s[(b + y1 * 64 + x1) * 64 + c4];
    float w00 = (1.f - wy) * (1.f - wx), w01 = (1.f - wy) * wx;
    float w10 = wy * (1.f - wx),         w11 = wy * wx;
    float4 r;
    r.x = v00.x * w00 + v01.x * w01 + v10.x * w10 + v11.x * w11;
    r.y = v00.y * w00 + v01.y * w01 + v10.y * w10 + v11.y * w11;
    r.z = v00.z * w00 + v01.z * w01 + v10.z * w10 + v11.z * w11;
    r.w = v00.w * w00 + v01.w * w01 + v10.w * w10 + v11.w * w11;
    ((float4*)out_t)[(size_t)p * 64 + c4] = r;
}

// ---------------- 1x1 conv as SGEMM: out[CO,P] = W[CO,CI] * X[CI,P] ----------------
// 128x128 tile, BK=16, 256 threads, 8x8 register tile, register double-buffered loads.
__global__ __launch_bounds__(256, 2)
void conv1x1_kernel(const float* __restrict__ in0, const float* __restrict__ in1,
                    int ci0, int CI, const float* __restrict__ Wt,
                    const float* __restrict__ gamma, const float* __restrict__ beta,
                    int relu, int nhwc,
                    float* __restrict__ out, int CO) {
    __shared__ __align__(16) float As[16][132];
    __shared__ __align__(16) float Bs[16][132];
    int t   = threadIdx.x;
    int qb  = blockIdx.x * 128;
    int cob = blockIdx.y * 128;
    int n   = qb >> 14;
    int hwb = qb & (HWD - 1);
    int tc  = (t & 15) * 8;
    int tr  = (t >> 4) * 8;

    int a_co = t >> 1, a_kq = (t & 1) * 8;
    int b_k  = t >> 4, b_px = (t & 15) * 8;     // nchw
    int c_px = t >> 1, c_kq = (t & 1) * 8;      // nhwc

    float acc[8][8];
    #pragma unroll
    for (int i = 0; i < 8; i++)
        #pragma unroll
        for (int j = 0; j < 8; j++) acc[i][j] = 0.f;

    float4 ra0, ra1, rb0, rb1;
    {
        ra0 = *(const float4*)&Wt[(size_t)(cob + a_co) * CI + a_kq];
        ra1 = *(const float4*)&Wt[(size_t)(cob + a_co) * CI + a_kq + 4];
        if (!nhwc) {
            int ci = b_k;
            const float* src = (ci < ci0)
                ? &in0[(size_t)((n * ci0 + ci) << 14) + hwb + b_px]
                : &in1[(size_t)((n * (CI - ci0) + (ci - ci0)) << 14) + hwb + b_px];
            rb0 = *(const float4*)src; rb1 = *(const float4*)(src + 4);
        } else {
            const float* src = &in0[((size_t)(n << 14) + hwb + c_px) * CIN + c_kq];
            rb0 = *(const float4*)src; rb1 = *(const float4*)(src + 4);
        }
    }

    for (int kb = 0; kb < CI; kb += 16) {
        As[a_kq + 0][a_co] = ra0.x; As[a_kq + 1][a_co] = ra0.y;
        As[a_kq + 2][a_co] = ra0.z; As[a_kq + 3][a_co] = ra0.w;
        As[a_kq + 4][a_co] = ra1.x; As[a_kq + 5][a_co] = ra1.y;
        As[a_kq + 6][a_co] = ra1.z; As[a_kq + 7][a_co] = ra1.w;
        if (!nhwc) {
            *(float4*)&Bs[b_k][b_px]     = rb0;
            *(float4*)&Bs[b_k][b_px + 4] = rb1;
        } else {
            Bs[c_kq + 0][c_px] = rb0.x; Bs[c_kq + 1][c_px] = rb0.y;
            Bs[c_kq + 2][c_px] = rb0.z; Bs[c_kq + 3][c_px] = rb0.w;
            Bs[c_kq + 4][c_px] = rb1.x; Bs[c_kq + 5][c_px] = rb1.y;
            Bs[c_kq + 6][c_px] = rb1.z; Bs[c_kq + 7][c_px] = rb1.w;
        }
        __syncthreads();
        int kn = kb + 16;
        if (kn < CI) {
            ra0 = *(const float4*)&Wt[(size_t)(cob + a_co) * CI + kn + a_kq];
            ra1 = *(const float4*)&Wt[(size_t)(cob + a_co) * CI + kn + a_kq + 4];
            if (!nhwc) {
                int ci = kn + b_k;
                const float* src = (ci < ci0)
                    ? &in0[(size_t)((n * ci0 + ci) << 14) + hwb + b_px]
                    : &in1[(size_t)((n * (CI - ci0) + (ci - ci0)) << 14) + hwb + b_px];
                rb0 = *(const float4*)src; rb1 = *(const float4*)(src + 4);
            } else {
                const float* src = &in0[((size_t)(n << 14) + hwb + c_px) * CIN + kn + c_kq];
                rb0 = *(const float4*)src; rb1 = *(const float4*)(src + 4);
            }
        }
        #pragma unroll
        for (int k = 0; k < 16; k++) {
            float4 a0 = *(const float4*)&As[k][tr];
            float4 a1 = *(const float4*)&As[k][tr + 4];
            float4 b0 = *(const float4*)&Bs[k][tc];
            float4 b1 = *(const float4*)&Bs[k][tc + 4];
            float av[8] = {a0.x, a0.y, a0.z, a0.w, a1.x, a1.y, a1.z, a1.w};
            float bv[8] = {b0.x, b0.y, b0.z, b0.w, b1.x, b1.y, b1.z, b1.w};
            #pragma unroll
            for (int i = 0; i < 8; i++)
                #pragma unroll
                for (int j = 0; j < 8; j++)
                    acc[i][j] += av[i] * bv[j];
        }
        __syncthreads();
    }

    const float rs = 1.0f / sqrtf(1.0f + 1e-5f);
    #pragma unroll
    for (int i = 0; i < 8; i++) {
        int co = cob + tr + i;
        float sc = 1.f, bi;
        if (gamma) { sc = gamma[co] * rs; bi = beta[co]; } else { bi = beta[co]; }
        float r[8];
        #pragma unroll
        for (int j = 0; j < 8; j++) {
            float v = acc[i][j];
            if (gamma) { v = v * sc + bi; if (relu) v = fmaxf(v, 0.f); }
            else v += bi;
            r[j] = v;
        }
        float* dst = &out[(size_t)((n * CO + co) << 14) + hwb + tc];
        *(float4*)dst       = make_float4(r[0], r[1], r[2], r[3]);
        *(float4*)(dst + 4) = make_float4(r[4], r[5], r[6], r[7]);
    }
}

// ---------------- grouped cosine sim + |cp1-sp1| ----------------
__global__ void simfdif_kernel(const float* __restrict__ cp1, const float* __restrict__ sp1,
                               float* __restrict__ fdif, float* __restrict__ sim) {
    int idx = blockIdx.x * 256 + threadIdx.x;
    int hw = idx & (HWD - 1);
    int ng = idx >> 14;
    int gi = ng & 7, n = ng >> 3;
    size_t base = (size_t)((n * C2 + gi * C2G) << 14) + hw;
    float num = 0.f, na = 0.f, nb = 0.f;
    #pragma unroll
    for (int c = 0; c < C2G; c++) {
        float a = cp1[base + ((size_t)c << 14)];
        float b = sp1[base + ((size_t)c << 14)];
        num += a * b; na += a * a; nb += b * b;
        fdif[base + ((size_t)c << 14)] = fabsf(a - b);
    }
    sim[((size_t)ng << 14) + hw] =
        num / (fmaxf(sqrtf(na), 1e-8f) * fmaxf(sqrtf(nb), 1e-8f));
}

// ---------------- 3x3 conv, pad 1, CO=32, register-prefetch double buffered ----------------
// grid: (W/32, H/8, NB); 256 threads: 64 pixel-quads x 4 co-octets
#define PS_ELEMS (4 * 10 * 34)   // 1360
#define WS_ELEMS (4 * 32 * 9)    // 1152
__global__ void conv3x3_kernel(const float* __restrict__ in, const float* __restrict__ wgt,
                               const float* __restrict__ bias, float* __restrict__ out, int CI) {
    __shared__ float ps[4][10][36];
    __shared__ __align__(16) float ws[4][9][32];
    int t  = threadIdx.x;
    int o  = t >> 6;
    int q  = t & 63;
    int ty = q >> 3;
    int tx = (q & 7) * 4;
    int n  = blockIdx.z;
    int y0 = blockIdx.y * 8, x0 = blockIdx.x * 32;
    float acc[8][4];
    #pragma unroll
    for (int a = 0; a < 8; a++)
        #pragma unroll
        for (int b = 0; b < 4; b++) acc[a][b] = 0.f;

    float pv[6], wv5[5];

    // prefetch cb = 0
    #pragma unroll
    for (int j = 0; j < 6; j++) {
        int i = t + j * 256;
        float v = 0.f;
        if (i < PS_ELEMS) {
            int cc = i / 340; int rem = i - cc * 340;
            int yy = rem / 34; int xx = rem - yy * 34;
            int gy = y0 + yy - 1, gx = x0 + xx - 1;
            if (gy >= 0 && gy < HH && gx >= 0 && gx < WW)
                v = in[(size_t)((n * CI + cc) << 14) + (gy << 7) + gx];
        }
        pv[j] = v;
    }
    #pragma unroll
    for (int j = 0; j < 5; j++) {
        int i = t + j * 256;
        float v = 0.f;
        if (i < WS_ELEMS) {
            int cc = i / 288; int rem = i - cc * 288;
            int tap = rem >> 5; int co = rem & 31;
            v = wgt[(size_t)(co * CI + cc) * 9 + tap];
        }
        wv5[j] = v;
    }

    for (int cb = 0; cb < CI; cb += 4) {
        __syncthreads();
        // regs -> smem
        #pragma unroll
        for (int j = 0; j < 6; j++) {
            int i = t + j * 256;
            if (i < PS_ELEMS) {
                int cc = i / 340; int rem = i - cc * 340;
                int yy = rem / 34; int xx = rem - yy * 34;
                ps[cc][yy][xx] = pv[j];
            }
        }
        #pragma unroll
        for (int j = 0; j < 5; j++) {
            int i = t + j * 256;
            if (i < WS_ELEMS) {
                int cc = i / 288; int rem = i - cc * 288;
                int tap = rem >> 5; int co = rem & 31;
                ws[cc][tap][co] = wv5[j];
            }
        }
        __syncthreads();
        // prefetch next chunk (LDGs overlap the compute below)
        int cn = cb + 4;
        if (cn < CI) {
            #pragma unroll
            for (int j = 0; j < 6; j++) {
                int i = t + j * 256;
                float v = 0.f;
                if (i < PS_ELEMS) {
                    int cc = i / 340; int rem = i - cc * 340;
                    int yy = rem / 34; int xx = rem - yy * 34;
                    int gy = y0 + yy - 1, gx = x0 + xx - 1;
                    if (gy >= 0 && gy < HH && gx >= 0 && gx < WW)
                        v = in[(size_t)((n * CI + cn + cc) << 14) + (gy << 7) + gx];
                }
                pv[j] = v;
            }
            #pragma unroll
            for (int j = 0; j < 5; j++) {
                int i = t + j * 256;
                float v = 0.f;
                if (i < WS_ELEMS) {
                    int cc = i / 288; int rem = i - cc * 288;
                    int tap = rem >> 5; int co = rem & 31;
                    v = wgt[(size_t)(co * CI + cn + cc) * 9 + tap];
                }
                wv5[j] = v;
            }
        }
        // compute
        #pragma unroll
        for (int cc = 0; cc < 4; cc++) {
            float p[3][6];
            #pragma unroll
            for (int yy = 0; yy < 3; yy++)
                #pragma unroll
                for (int xx = 0; xx < 6; xx++)
                    p[yy][xx] = ps[cc][ty + yy][tx + xx];
            #pragma unroll
            for (int tap = 0; tap < 9; tap++) {
                int ky = tap / 3, kx = tap - ky * 3;
                float4 w0 = *(const float4*)&ws[cc][tap][o * 8];
                float4 w1 = *(const float4*)&ws[cc][tap][o * 8 + 4];
                float wv[8] = {w0.x, w0.y, w0.z, w0.w, w1.x, w1.y, w1.z, w1.w};
                #pragma unroll
                for (int c8 = 0; c8 < 8; c8++) {
                    acc[c8][0] += wv[c8] * p[ky][kx + 0];
                    acc[c8][1] += wv[c8] * p[ky][kx + 1];
                    acc[c8][2] += wv[c8] * p[ky][kx + 2];
                    acc[c8][3] += wv[c8] * p[ky][kx + 3];
                }
            }
        }
    }
    #pragma unroll
    for (int c8 = 0; c8 < 8; c8++) {
        int co = o * 8 + c8;
        float b = bias[co];
        size_t ob = (size_t)((n * 32 + co) << 14) + ((y0 + ty) << 7) + x0 + tx;
        #pragma unroll
        for (int j = 0; j < 4; j++) out[ob + j] = acc[c8][j] + b;
    }
}

// ---------------- fused off 1x1 conv + dual grid_sample ----------------
__device__ __forceinline__ float4 sample32(const float* __restrict__ src_t, int n,
                                           int chan4, float gx, float gy) {
    float x0f = floorf(gx), y0f = floorf(gy);
    int x0 = (int)x0f, y0 = (int)y0f;
    float wx = gx - x0f, wy = gy - y0f;
    bool vx0 = (x0 >= 0) & (x0 <= WW - 1);
    bool vx1 = (x0 + 1 >= 0) & (x0 + 1 <= WW - 1);
    bool vy0 = (y0 >= 0) & (y0 <= HH - 1);
    bool vy1 = (y0 + 1 >= 0) & (y0 + 1 <= HH - 1);
    float c00 = (vx0 && vy0) ? (1.f - wx) * (1.f - wy) : 0.f;
    float c01 = (vx1 && vy0) ? wx * (1.f - wy) : 0.f;
    float c10 = (vx0 && vy1) ? (1.f - wx) * wy : 0.f;
    float c11 = (vx1 && vy1) ? wx * wy : 0.f;
    int xc0 = min(max(x0, 0), WW - 1), xc1 = min(max(x0 + 1, 0), WW - 1);
    int yc0 = min(max(y0, 0), HH - 1), yc1 = min(max(y0 + 1, 0), HH - 1);
    const float4* p = (const float4*)src_t;
    size_t b = (size_t)(n << 14);
    float4 v00 = p[(b + (yc0 << 7) + xc0) * 64 + chan4];
    float4 v01 = p[(b + (yc0 << 7) + xc1) * 64 + chan4];
    float4 v10 = p[(b + (yc1 << 7) + xc0) * 64 + chan4];
    float4 v11 = p[(b + (yc1 << 7) + xc1) * 64 + chan4];
    float4 r;
    r.x = v00.x * c00 + v01.x * c01 + v10.x * c10 + v11.x * c11;
    r.y = v00.y * c00 + v01.y * c01 + v10.y * c10 + v11.y * c11;
    r.z = v00.z * c00 + v01.z * c01 + v10.z * c10 + v11.z * c11;
    r.w = v00.w * c00 + v01.w * c01 + v10.w * c10 + v11.w * c11;
    return r;
}

__global__ void offgrid_kernel(const float* __restrict__ redim, const float* __restrict__ fdir,
                               const float* __restrict__ fdist, const float* __restrict__ Wofft,
                               const float* __restrict__ boff, const float* __restrict__ cp_t,
                               const float* __restrict__ spup_t, float* __restrict__ out) {
    __shared__ float buf[256 * 32];
    __shared__ float off_s[32][33];
    int t   = threadIdx.x;
    int qb  = blockIdx.x * 32;
    int n   = qb >> 14;
    int hwb = qb & (HWD - 1);
    int lane = t & 31, wid = t >> 5;

    for (int i = t; i < 192 * 32; i += 256) {
        int ci = i >> 5; int px = i & 31; int hw = hwb + px;
        float v;
        if (ci < 128)      v = redim[(size_t)((n * C2 + ci) << 14) + hw];
        else if (ci < 160) v = fdir[(size_t)((n * 32 + ci - 128) << 14) + hw];
        else               v = fdist[(size_t)((n * 32 + ci - 160) << 14) + hw];
        buf[i] = v;
    }
    __syncthreads();
    {
        float a0 = 0.f, a1 = 0.f, a2 = 0.f, a3 = 0.f;
        const float4* wt = (const float4*)Wofft;
        #pragma unroll 4
        for (int ci = 0; ci < 192; ci++) {
            float4 wv = __ldg(&wt[ci * 8 + wid]);
            float x = buf[ci * 32 + lane];
            a0 += wv.x * x; a1 += wv.y * x; a2 += wv.z * x; a3 += wv.w * x;
        }
        off_s[lane][wid * 4 + 0] = a0 + __ldg(&boff[wid * 4 + 0]);
        off_s[lane][wid * 4 + 1] = a1 + __ldg(&boff[wid * 4 + 1]);
        off_s[lane][wid * 4 + 2] = a2 + __ldg(&boff[wid * 4 + 2]);
        off_s[lane][wid * 4 + 3] = a3 + __ldg(&boff[wid * 4 + 3]);
    }
    __syncthreads();

    int gi = wid;
    int cc4  = lane & 7; int sub = lane >> 3;
    const float K = 127.0f / 256.0f;
    for (int it = 0; it < 8; it++) {
        int px = it * 4 + sub;
        int hw = hwb + px;
        int ox = hw & 127, oy = hw >> 7;
        float olx = off_s[px][2 * gi],      oly = off_s[px][2 * gi + 1];
        float ohx = off_s[px][16 + 2 * gi], ohy = off_s[px][16 + 2 * gi + 1];
        int chan4 = gi * 8 + cc4;
        float4 a = sample32(cp_t,   n, chan4, (float)ox + olx * K, (float)oy + oly * K);
        float4 b = sample32(spup_t, n, chan4, (float)ox + ohx * K, (float)oy + ohy * K);
        int cbase = (gi * 32 + cc4 * 4) * 32 + px;
        buf[cbase + 0]  = a.x + b.x;
        buf[cbase + 32] = a.y + b.y;
        buf[cbase + 64] = a.z + b.z;
        buf[cbase + 96] = a.w + b.w;
    }
    __syncthreads();
    for (int i = t; i < 256 * 32; i += 256) {
        int c = i >> 5; int px = i & 31;
        out[(size_t)((n * 256 + c) << 14) + hwb + px] = buf[i];
    }
}

// ---------------- launch ----------------
extern "C" void kernel_launch(void* const* d_in, const int* in_sizes, int n_in,
                              void* d_out, int out_size) {
    const float* cp      = (const float*)d_in[0];
    const float* sp      = (const float*)d_in[1];
    const float* w_cp    = (const float*)d_in[2];
    const float* gm_cp   = (const float*)d_in[3];
    const float* b_cp    = (const float*)d_in[4];
    const float* w_sp    = (const float*)d_in[5];
    const float* gm_sp   = (const float*)d_in[6];
    const float* b_sp    = (const float*)d_in[7];
    const float* w_redim = (const float*)d_in[8];
    const float* b_redim = (const float*)d_in[9];
    const float* w_dir   = (const float*)d_in[10];
    const float* b_dir   = (const float*)d_in[11];
    const float* w_dist  = (const float*)d_in[12];
    const float* b_dist  = (const float*)d_in[13];
    const float* w_off   = (const float*)d_in[14];
    const float* b_off   = (const float*)d_in[15];
    float* out = (float*)d_out;

    float* sp_t   = nullptr; cudaGetSymbolAddress((void**)&sp_t,   g_sp_t);
    float* cp_t   = nullptr; cudaGetSymbolAddress((void**)&cp_t,   g_cp_t);
    float* spup_t = nullptr; cudaGetSymbolAddress((void**)&spup_t, g_spup_t);
    float* cp1    = nullptr; cudaGetSymbolAddress((void**)&cp1,    g_cp1);
    float* sp1    = nullptr; cudaGetSymbolAddress((void**)&sp1,    g_sp1);
    float* redim  = nullptr; cudaGetSymbolAddress((void**)&redim,  g_redim);
    float* sim    = nullptr; cudaGetSymbolAddress((void**)&sim,    g_sim);
    float* fdif   = nullptr; cudaGetSymbolAddress((void**)&fdif,   g_fdif);
    float* fdir   = nullptr; cudaGetSymbolAddress((void**)&fdir,   g_fdir);
    float* fdist  = nullptr; cudaGetSymbolAddress((void**)&fdist,  g_fdist);
    float* wofft  = nullptr; cudaGetSymbolAddress((void**)&wofft,  g_wofft);

    transpose_kernel<<<dim3(HWD / 32, CIN / 32, NB), 256>>>(cp, cp_t, CIN, HWD);
    transpose_kernel<<<dim3(SHW / 32, CIN / 32, NB), 256>>>(sp, sp_t, CIN, SHW);
    woff_transpose_kernel<<<24, 256>>>(w_off, wofft);
    upsample_kernel<<<(NB * HWD * 64) / 256, 256>>>(sp_t, spup_t);
    // cp1 = bn_relu(conv1x1(cp))          [NCHW in]
    conv1x1_kernel<<<dim3(NHW / 128, C2 / 128), 256>>>(cp, nullptr, CIN, CIN, w_cp,
                                                       gm_cp, b_cp, 1, 0, cp1, C2);
    // sp1 = bn_relu(conv1x1(sp_up))       [NHWC in]
    conv1x1_kernel<<<dim3(NHW / 128, C2 / 128), 256>>>(spup_t, nullptr, CIN, CIN, w_sp,
                                                       gm_sp, b_sp, 1, 1, sp1, C2);
    // redim = conv1x1(concat(cp1, sp1)) + b
    conv1x1_kernel<<<dim3(NHW / 128, C2 / 128), 256>>>(cp1, sp1, C2, 2 * C2, w_redim,
                                                       nullptr, b_redim, 0, 0, redim, C2);
    simfdif_kernel<<<(NB * GR * HWD) / 256, 256>>>(cp1, sp1, fdif, sim);
    conv3x3_kernel<<<dim3(WW / 32, HH / 8, NB), 256>>>(sim, w_dir, b_dir, fdir, GR);
    conv3x3_kernel<<<dim3(WW / 32, HH / 8, NB), 256>>>(fdif, w_dist, b_dist, fdist, C2);
    offgrid_kernel<<<NHW / 32, 256>>>(redim, fdir, fdist, wofft, b_off, cp_t, spup_t, out);
}

// round 12
// speedup vs baseline: 1.3991x; 1.1463x over previous
#include <cuda_runtime.h>
#include <math.h>
#include <stdint.h>

// ---------------- problem constants ----------------
#define NB     8
#define CIN    256
#define HH     128
#define WW     128
#define HWD    16384            // HH*WW
#define NHW    131072           // NB*HWD
#define C2     128
#define GR     8
#define C2G    16               // C2/GR
#define SH     64               // sp spatial
#define SHW    4096             // 64*64

// ---------------- scratch (device globals; no allocs allowed) ----------------
__device__ float g_sp_t[NB * SHW * CIN];        // sp  NHWC (sampler path)
__device__ float g_cp_t[NB * HWD * CIN];        // cp  NHWC (sampler)
__device__ float g_spup_t[NB * HWD * CIN];      // sp_up NHWC (sampler)
__device__ float g_z[NB * C2 * SHW];            // low-res conv_bn(sp) affine
__device__ float g_cp1[NB * C2 * HWD];          // NCHW
__device__ float g_sp1[NB * C2 * HWD];
__device__ float g_redim[NB * C2 * HWD];
__device__ float g_sim[NB * GR * HWD];
__device__ float g_fdif[NB * C2 * HWD];
__device__ float g_fdir[NB * 32 * HWD];
__device__ float g_fdist[NB * 32 * HWD];
__device__ float g_wofft[192 * 32];             // w_off transposed [ci][co]

// ---------------- cp.async helpers ----------------
__device__ __forceinline__ void cp_async16(float* dst, const float* src) {
    uint32_t a = (uint32_t)__cvta_generic_to_shared(dst);
    asm volatile("cp.async.cg.shared.global [%0], [%1], 16;" :: "r"(a), "l"(src));
}
#define CP_COMMIT() asm volatile("cp.async.commit_group;" ::: "memory")
#define CP_WAIT0()  asm volatile("cp.async.wait_group 0;" ::: "memory")

// ---------------- transpose NCHW -> NHWC ----------------
__global__ void transpose_kernel(const float* __restrict__ in, float* __restrict__ out,
                                 int C, int HW) {
    __shared__ float tile[32][33];
    int hwb = blockIdx.x * 32, cb = blockIdx.y * 32, n = blockIdx.z;
    int lane = threadIdx.x & 31, row = threadIdx.x >> 5;
    #pragma unroll
    for (int r = row; r < 32; r += 8)
        tile[r][lane] = in[(size_t)(n * C + cb + r) * HW + hwb + lane];
    __syncthreads();
    #pragma unroll
    for (int r = row; r < 32; r += 8)
        out[((size_t)n * HW + hwb + r) * C + cb + lane] = tile[lane][r];
}

// ---------------- transpose w_off [32][192] -> [192][32] ----------------
__global__ void woff_transpose_kernel(const float* __restrict__ w, float* __restrict__ wt) {
    int i = blockIdx.x * 256 + threadIdx.x;
    if (i < 32 * 192) {
        int co = i / 192, ci = i - co * 192;
        wt[ci * 32 + co] = w[i];
    }
}

// ---------------- bilinear upsample (align_corners) in NHWC (sampler source) ----------------
__global__ void upsample_kernel(const float* __restrict__ sp_t, float* __restrict__ out_t) {
    int idx = blockIdx.x * 256 + threadIdx.x;          // over NB*HWD*64 float4s
    int c4 = idx & 63;
    int p  = idx >> 6;
    int hw = p & (HWD - 1);
    int n  = p >> 14;
    int oy = hw >> 7, ox = hw & 127;
    float sy = oy * (63.0f / 127.0f);
    float sx = ox * (63.0f / 127.0f);
    int y0 = (int)sy; float wy = sy - (float)y0; int y1 = min(y0 + 1, 63);
    int x0 = (int)sx; float wx = sx - (float)x0; int x1 = min(x0 + 1, 63);
    const float4* s = (const float4*)sp_t;
    size_t b = (size_t)n * SHW;
    float4 v00 = s[(b + y0 * 64 + x0) * 64 + c4];
    float4 v01 = s[(b + y0 * 64 + x1) * 64 + c4];
    float4 v10 = s[(b + y1 * 64 + x0) * 64 + c4];
    float4 v11 = s[(b + y1 * 64 + x1) * 64 + c4];
    float w00 = (1.f - wy) * (1.f - wx), w01 = (1.f - wy) * wx;
    float w10 = wy * (1.f - wx),         w11 = wy * wx;
    float4 r;
    r.x = v00.x * w00 + v01.x * w01 + v10.x * w10 + v11.x * w11;
    r.y = v00.y * w00 + v01.y * w01 + v10.y * w10 + v11.y * w11;
    r.z = v00.z * w00 + v01.z * w01 + v10.z * w10 + v11.z * w11;
    r.w = v00.w * w00 + v01.w * w01 + v10.w * w10 + v11.w * w11;
    ((float4*)out_t)[(size_t)p * 64 + c4] = r;
}

// ---------------- bilinear upsample NCHW + ReLU (sp1 = relu(interp(z))) ----------------
__global__ void upsample_relu_kernel(const float* __restrict__ z, float* __restrict__ out) {
    int idx = blockIdx.x * 256 + threadIdx.x;     // over NB*C2*HWD
    int hw = idx & (HWD - 1);
    int nc = idx >> 14;
    int oy = hw >> 7, ox = hw & 127;
    float sy = oy * (63.0f / 127.0f);
    float sx = ox * (63.0f / 127.0f);
    int y0 = (int)sy; float wy = sy - (float)y0; int y1 = min(y0 + 1, 63);
    int x0 = (int)sx; float wx = sx - (float)x0; int x1 = min(x0 + 1, 63);
    const float* b = z + ((size_t)nc << 12);
    float v = (b[y0 * 64 + x0] * (1.f - wx) + b[y0 * 64 + x1] * wx) * (1.f - wy)
            + (b[y1 * 64 + x0] * (1.f - wx) + b[y1 * 64 + x1] * wx) * wy;
    out[idx] = fmaxf(v, 0.f);
}

// ---------------- 1x1 conv as SGEMM (NCHW): out[CO,P] = W[CO,CI] * X[CI,P] ----------------
// 128x128 tile, BK=16, 256 threads, 8x8 reg tile; cp.async 2-stage for B,
// register prefetch for A, ONE syncthreads per K-block.
// relu<0 : pure affine (BN scale+bias, no relu).  gamma==null: +beta only.
__global__ __launch_bounds__(256, 2)
void conv1x1_kernel(const float* __restrict__ in0, const float* __restrict__ in1,
                    int ci0, int CI, int hwshift, const float* __restrict__ Wt,
                    const float* __restrict__ gamma, const float* __restrict__ beta,
                    int relu, float* __restrict__ out, int CO) {
    __shared__ __align__(16) float As[2][16][132];
    __shared__ __align__(16) float Bs[2][16][132];
    int t   = threadIdx.x;
    int qb  = blockIdx.x * 128;
    int cob = blockIdx.y * 128;
    int hwmask = (1 << hwshift) - 1;
    int n   = qb >> hwshift;
    int hwb = qb & hwmask;
    int tc  = (t & 15) * 8;
    int tr  = (t >> 4) * 8;
    int a_co = t >> 1, a_kq = (t & 1) * 8;
    int b_k  = t >> 4, b_px = (t & 15) * 8;

    float acc[8][8];
    #pragma unroll
    for (int i = 0; i < 8; i++)
        #pragma unroll
        for (int j = 0; j < 8; j++) acc[i][j] = 0.f;

    // prologue: B stage 0 via cp.async, A stage 0 into regs
    {
        int ci = b_k;
        const float* s0 = (ci < ci0)
            ? &in0[(((size_t)(n * ci0 + ci)) << hwshift) + hwb + b_px]
            : &in1[(((size_t)(n * (CI - ci0) + (ci - ci0))) << hwshift) + hwb + b_px];
        cp_async16(&Bs[0][b_k][b_px], s0);
        cp_async16(&Bs[0][b_k][b_px + 4], s0 + 4);
        CP_COMMIT();
    }
    float4 ra0 = *(const float4*)&Wt[(size_t)(cob + a_co) * CI + a_kq];
    float4 ra1 = *(const float4*)&Wt[(size_t)(cob + a_co) * CI + a_kq + 4];

    int s = 0;
    for (int kb = 0; kb < CI; kb += 16, s ^= 1) {
        As[s][a_kq + 0][a_co] = ra0.x; As[s][a_kq + 1][a_co] = ra0.y;
        As[s][a_kq + 2][a_co] = ra0.z; As[s][a_kq + 3][a_co] = ra0.w;
        As[s][a_kq + 4][a_co] = ra1.x; As[s][a_kq + 5][a_co] = ra1.y;
        As[s][a_kq + 6][a_co] = ra1.z; As[s][a_kq + 7][a_co] = ra1.w;
        CP_WAIT0();
        __syncthreads();
        int kn = kb + 16;
        if (kn < CI) {
            int ci = kn + b_k;
            const float* sn = (ci < ci0)
                ? &in0[(((size_t)(n * ci0 + ci)) << hwshift) + hwb + b_px]
                : &in1[(((size_t)(n * (CI - ci0) + (ci - ci0))) << hwshift) + hwb + b_px];
            cp_async16(&Bs[s ^ 1][b_k][b_px], sn);
            cp_async16(&Bs[s ^ 1][b_k][b_px + 4], sn + 4);
            CP_COMMIT();
            ra0 = *(const float4*)&Wt[(size_t)(cob + a_co) * CI + kn + a_kq];
            ra1 = *(const float4*)&Wt[(size_t)(cob + a_co) * CI + kn + a_kq + 4];
        }
        #pragma unroll
        for (int k = 0; k < 16; k++) {
            float4 a0 = *(const float4*)&As[s][k][tr];
            float4 a1 = *(const float4*)&As[s][k][tr + 4];
            float4 b0 = *(const float4*)&Bs[s][k][tc];
            float4 b1 = *(const float4*)&Bs[s][k][tc + 4];
            float av[8] = {a0.x, a0.y, a0.z, a0.w, a1.x, a1.y, a1.z, a1.w};
            float bv[8] = {b0.x, b0.y, b0.z, b0.w, b1.x, b1.y, b1.z, b1.w};
            #pragma unroll
            for (int i = 0; i < 8; i++)
                #pragma unroll
                for (int j = 0; j < 8; j++)
                    acc[i][j] += av[i] * bv[j];
        }
    }

    const float rs = 1.0f / sqrtf(1.0f + 1e-5f);
    #pragma unroll
    for (int i = 0; i < 8; i++) {
        int co = cob + tr + i;
        float sc = 1.f, bi;
        if (gamma) { sc = gamma[co] * rs; bi = beta[co]; } else { bi = beta[co]; }
        float r[8];
        #pragma unroll
        for (int j = 0; j < 8; j++) {
            float v = acc[i][j];
            if (gamma) { v = v * sc + bi; if (relu > 0) v = fmaxf(v, 0.f); }
            else v += bi;
            r[j] = v;
        }
        float* dst = &out[(((size_t)(n * CO + co)) << hwshift) + hwb + tc];
        *(float4*)dst       = make_float4(r[0], r[1], r[2], r[3]);
        *(float4*)(dst + 4) = make_float4(r[4], r[5], r[6], r[7]);
    }
}

// ---------------- grouped cosine sim + |cp1-sp1| ----------------
__global__ void simfdif_kernel(const float* __restrict__ cp1, const float* __restrict__ sp1,
                               float* __restrict__ fdif, float* __restrict__ sim) {
    int idx = blockIdx.x * 256 + threadIdx.x;
    int hw = idx & (HWD - 1);
    int ng = idx >> 14;
    int gi = ng & 7, n = ng >> 3;
    size_t base = (size_t)((n * C2 + gi * C2G) << 14) + hw;
    float num = 0.f, na = 0.f, nb = 0.f;
    #pragma unroll
    for (int c = 0; c < C2G; c++) {
        float a = cp1[base + ((size_t)c << 14)];
        float b = sp1[base + ((size_t)c << 14)];
        num += a * b; na += a * a; nb += b * b;
        fdif[base + ((size_t)c << 14)] = fabsf(a - b);
    }
    sim[((size_t)ng << 14) + hw] =
        num / (fmaxf(sqrtf(na), 1e-8f) * fmaxf(sqrtf(nb), 1e-8f));
}

// ---------------- 3x3 conv, pad 1, CO=32, register-prefetch double buffered ----------------
#define PS_ELEMS (4 * 10 * 34)   // 1360
#define WS_ELEMS (4 * 32 * 9)    // 1152
__global__ void conv3x3_kernel(const float* __restrict__ in, const float* __restrict__ wgt,
                               const float* __restrict__ bias, float* __restrict__ out, int CI) {
    __shared__ float ps[4][10][36];
    __shared__ __align__(16) float ws[4][9][32];
    int t  = threadIdx.x;
    int o  = t >> 6;
    int q  = t & 63;
    int ty = q >> 3;
    int tx = (q & 7) * 4;
    int n  = blockIdx.z;
    int y0 = blockIdx.y * 8, x0 = blockIdx.x * 32;
    float acc[8][4];
    #pragma unroll
    for (int a = 0; a < 8; a++)
        #pragma unroll
        for (int b = 0; b < 4; b++) acc[a][b] = 0.f;

    float pv[6], wv5[5];

    #pragma unroll
    for (int j = 0; j < 6; j++) {
        int i = t + j * 256;
        float v = 0.f;
        if (i < PS_ELEMS) {
            int cc = i / 340; int rem = i - cc * 340;
            int yy = rem / 34; int xx = rem - yy * 34;
            int gy = y0 + yy - 1, gx = x0 + xx - 1;
            if (gy >= 0 && gy < HH && gx >= 0 && gx < WW)
                v = in[(size_t)((n * CI + cc) << 14) + (gy << 7) + gx];
        }
        pv[j] = v;
    }
    #pragma unroll
    for (int j = 0; j < 5; j++) {
        int i = t + j * 256;
        float v = 0.f;
        if (i < WS_ELEMS) {
            int cc = i / 288; int rem = i - cc * 288;
            int tap = rem >> 5; int co = rem & 31;
            v = wgt[(size_t)(co * CI + cc) * 9 + tap];
        }
        wv5[j] = v;
    }

    for (int cb = 0; cb < CI; cb += 4) {
        __syncthreads();
        #pragma unroll
        for (int j = 0; j < 6; j++) {
            int i = t + j * 256;
            if (i < PS_ELEMS) {
                int cc = i / 340; int rem = i - cc * 340;
                int yy = rem / 34; int xx = rem - yy * 34;
                ps[cc][yy][xx] = pv[j];
            }
        }
        #pragma unroll
        for (int j = 0; j < 5; j++) {
            int i = t + j * 256;
            if (i < WS_ELEMS) {
                int cc = i / 288; int rem = i - cc * 288;
                int tap = rem >> 5; int co = rem & 31;
                ws[cc][tap][co] = wv5[j];
            }
        }
        __syncthreads();
        int cn = cb + 4;
        if (cn < CI) {
            #pragma unroll
            for (int j = 0; j < 6; j++) {
                int i = t + j * 256;
                float v = 0.f;
                if (i < PS_ELEMS) {
                    int cc = i / 340; int rem = i - cc * 340;
                    int yy = rem / 34; int xx = rem - yy * 34;
                    int gy = y0 + yy - 1, gx = x0 + xx - 1;
                    if (gy >= 0 && gy < HH && gx >= 0 && gx < WW)
                        v = in[(size_t)((n * CI + cn + cc) << 14) + (gy << 7) + gx];
                }
                pv[j] = v;
            }
            #pragma unroll
            for (int j = 0; j < 5; j++) {
                int i = t + j * 256;
                float v = 0.f;
                if (i < WS_ELEMS) {
                    int cc = i / 288; int rem = i - cc * 288;
                    int tap = rem >> 5; int co = rem & 31;
                    v = wgt[(size_t)(co * CI + cn + cc) * 9 + tap];
                }
                wv5[j] = v;
            }
        }
        #pragma unroll
        for (int cc = 0; cc < 4; cc++) {
            float p[3][6];
            #pragma unroll
            for (int yy = 0; yy < 3; yy++)
                #pragma unroll
                for (int xx = 0; xx < 6; xx++)
                    p[yy][xx] = ps[cc][ty + yy][tx + xx];
            #pragma unroll
            for (int tap = 0; tap < 9; tap++) {
                int ky = tap / 3, kx = tap - ky * 3;
                float4 w0 = *(const float4*)&ws[cc][tap][o * 8];
                float4 w1 = *(const float4*)&ws[cc][tap][o * 8 + 4];
                float wv[8] = {w0.x, w0.y, w0.z, w0.w, w1.x, w1.y, w1.z, w1.w};
                #pragma unroll
                for (int c8 = 0; c8 < 8; c8++) {
                    acc[c8][0] += wv[c8] * p[ky][kx + 0];
                    acc[c8][1] += wv[c8] * p[ky][kx + 1];
                    acc[c8][2] += wv[c8] * p[ky][kx + 2];
                    acc[c8][3] += wv[c8] * p[ky][kx + 3];
                }
            }
        }
    }
    #pragma unroll
    for (int c8 = 0; c8 < 8; c8++) {
        int co = o * 8 + c8;
        float b = bias[co];
        size_t ob = (size_t)((n * 32 + co) << 14) + ((y0 + ty) << 7) + x0 + tx;
        #pragma unroll
        for (int j = 0; j < 4; j++) out[ob + j] = acc[c8][j] + b;
    }
}

// ---------------- fused off 1x1 conv + dual grid_sample ----------------
__device__ __forceinline__ float4 sample32(const float* __restrict__ src_t, int n,
                                           int chan4, float gx, float gy) {
    float x0f = floorf(gx), y0f = floorf(gy);
    int x0 = (int)x0f, y0 = (int)y0f;
    float wx = gx - x0f, wy = gy - y0f;
    bool vx0 = (x0 >= 0) & (x0 <= WW - 1);
    bool vx1 = (x0 + 1 >= 0) & (x0 + 1 <= WW - 1);
    bool vy0 = (y0 >= 0) & (y0 <= HH - 1);
    bool vy1 = (y0 + 1 >= 0) & (y0 + 1 <= HH - 1);
    float c00 = (vx0 && vy0) ? (1.f - wx) * (1.f - wy) : 0.f;
    float c01 = (vx1 && vy0) ? wx * (1.f - wy) : 0.f;
    float c10 = (vx0 && vy1) ? (1.f - wx) * wy : 0.f;
    float c11 = (vx1 && vy1) ? wx * wy : 0.f;
    int xc0 = min(max(x0, 0), WW - 1), xc1 = min(max(x0 + 1, 0), WW - 1);
    int yc0 = min(max(y0, 0), HH - 1), yc1 = min(max(y0 + 1, 0), HH - 1);
    const float4* p = (const float4*)src_t;
    size_t b = (size_t)(n << 14);
    float4 v00 = p[(b + (yc0 << 7) + xc0) * 64 + chan4];
    float4 v01 = p[(b + (yc0 << 7) + xc1) * 64 + chan4];
    float4 v10 = p[(b + (yc1 << 7) + xc0) * 64 + chan4];
    float4 v11 = p[(b + (yc1 << 7) + xc1) * 64 + chan4];
    float4 r;
    r.x = v00.x * c00 + v01.x * c01 + v10.x * c10 + v11.x * c11;
    r.y = v00.y * c00 + v01.y * c01 + v10.y * c10 + v11.y * c11;
    r.z = v00.z * c00 + v01.z * c01 + v10.z * c10 + v11.z * c11;
    r.w = v00.w * c00 + v01.w * c01 + v10.w * c10 + v11.w * c11;
    return r;
}

__global__ void offgrid_kernel(const float* __restrict__ redim, const float* __restrict__ fdir,
                               const float* __restrict__ fdist, const float* __restrict__ Wofft,
                               const float* __restrict__ boff, const float* __restrict__ cp_t,
                               const float* __restrict__ spup_t, float* __restrict__ out) {
    __shared__ float buf[256 * 32];
    __shared__ float off_s[32][33];
    int t   = threadIdx.x;
    int qb  = blockIdx.x * 32;
    int n   = qb >> 14;
    int hwb = qb & (HWD - 1);
    int lane = t & 31, wid = t >> 5;

    for (int i = t; i < 192 * 32; i += 256) {
        int ci = i >> 5; int px = i & 31; int hw = hwb + px;
        float v;
        if (ci < 128)      v = redim[(size_t)((n * C2 + ci) << 14) + hw];
        else if (ci < 160) v = fdir[(size_t)((n * 32 + ci - 128) << 14) + hw];
        else               v = fdist[(size_t)((n * 32 + ci - 160) << 14) + hw];
        buf[i] = v;
    }
    __syncthreads();
    {
        float a0 = 0.f, a1 = 0.f, a2 = 0.f, a3 = 0.f;
        const float4* wt = (const float4*)Wofft;
        #pragma unroll 4
        for (int ci = 0; ci < 192; ci++) {
            float4 wv = __ldg(&wt[ci * 8 + wid]);
            float x = buf[ci * 32 + lane];
            a0 += wv.x * x; a1 += wv.y * x; a2 += wv.z * x; a3 += wv.w * x;
        }
        off_s[lane][wid * 4 + 0] = a0 + __ldg(&boff[wid * 4 + 0]);
        off_s[lane][wid * 4 + 1] = a1 + __ldg(&boff[wid * 4 + 1]);
        off_s[lane][wid * 4 + 2] = a2 + __ldg(&boff[wid * 4 + 2]);
        off_s[lane][wid * 4 + 3] = a3 + __ldg(&boff[wid * 4 + 3]);
    }
    __syncthreads();

    int gi = wid;
    int cc4  = lane & 7; int sub = lane >> 3;
    const float K = 127.0f / 256.0f;
    for (int it = 0; it < 8; it++) {
        int px = it * 4 + sub;
        int hw = hwb + px;
        int ox = hw & 127, oy = hw >> 7;
        float olx = off_s[px][2 * gi],      oly = off_s[px][2 * gi + 1];
        float ohx = off_s[px][16 + 2 * gi], ohy = off_s[px][16 + 2 * gi + 1];
        int chan4 = gi * 8 + cc4;
        float4 a = sample32(cp_t,   n, chan4, (float)ox + olx * K, (float)oy + oly * K);
        float4 b = sample32(spup_t, n, chan4, (float)ox + ohx * K, (float)oy + ohy * K);
        int cbase = (gi * 32 + cc4 * 4) * 32 + px;
        buf[cbase + 0]  = a.x + b.x;
        buf[cbase + 32] = a.y + b.y;
        buf[cbase + 64] = a.z + b.z;
        buf[cbase + 96] = a.w + b.w;
    }
    __syncthreads();
    for (int i = t; i < 256 * 32; i += 256) {
        int c = i >> 5; int px = i & 31;
        out[(size_t)((n * 256 + c) << 14) + hwb + px] = buf[i];
    }
}

// ---------------- launch ----------------
extern "C" void kernel_launch(void* const* d_in, const int* in_sizes, int n_in,
                              void* d_out, int out_size) {
    const float* cp      = (const float*)d_in[0];
    const float* sp      = (const float*)d_in[1];
    const float* w_cp    = (const float*)d_in[2];
    const float* gm_cp   = (const float*)d_in[3];
    const float* b_cp    = (const float*)d_in[4];
    const float* w_sp    = (const float*)d_in[5];
    const float* gm_sp   = (const float*)d_in[6];
    const float* b_sp    = (const float*)d_in[7];
    const float* w_redim = (const float*)d_in[8];
    const float* b_redim = (const float*)d_in[9];
    const float* w_dir   = (const float*)d_in[10];
    const float* b_dir   = (const float*)d_in[11];
    const float* w_dist  = (const float*)d_in[12];
    const float* b_dist  = (const float*)d_in[13];
    const float* w_off   = (const float*)d_in[14];
    const float* b_off   = (const float*)d_in[15];
    float* out = (float*)d_out;

    float* sp_t   = nullptr; cudaGetSymbolAddress((void**)&sp_t,   g_sp_t);
    float* cp_t   = nullptr; cudaGetSymbolAddress((void**)&cp_t,   g_cp_t);
    float* spup_t = nullptr; cudaGetSymbolAddress((void**)&spup_t, g_spup_t);
    float* zlo    = nullptr; cudaGetSymbolAddress((void**)&zlo,    g_z);
    float* cp1    = nullptr; cudaGetSymbolAddress((void**)&cp1,    g_cp1);
    float* sp1    = nullptr; cudaGetSymbolAddress((void**)&sp1,    g_sp1);
    float* redim  = nullptr; cudaGetSymbolAddress((void**)&redim,  g_redim);
    float* sim    = nullptr; cudaGetSymbolAddress((void**)&sim,    g_sim);
    float* fdif   = nullptr; cudaGetSymbolAddress((void**)&fdif,   g_fdif);
    float* fdir   = nullptr; cudaGetSymbolAddress((void**)&fdir,   g_fdir);
    float* fdist  = nullptr; cudaGetSymbolAddress((void**)&fdist,  g_fdist);
    float* wofft  = nullptr; cudaGetSymbolAddress((void**)&wofft,  g_wofft);

    // sampler-path transposes + NHWC upsample
    transpose_kernel<<<dim3(HWD / 32, CIN / 32, NB), 256>>>(cp, cp_t, CIN, HWD);
    transpose_kernel<<<dim3(SHW / 32, CIN / 32, NB), 256>>>(sp, sp_t, CIN, SHW);
    woff_transpose_kernel<<<24, 256>>>(w_off, wofft);
    upsample_kernel<<<(NB * HWD * 64) / 256, 256>>>(sp_t, spup_t);

    // z = affine_bn(conv1x1(sp)) at 64x64   (relu deferred to after upsample)
    conv1x1_kernel<<<dim3((NB * SHW) / 128, 1), 256>>>(sp, nullptr, CIN, CIN, 12, w_sp,
                                                       gm_sp, b_sp, -1, zlo, C2);
    // sp1 = relu(upsample(z))   — exact: conv+BN commute with bilinear interp
    upsample_relu_kernel<<<(NB * C2 * HWD) / 256, 256>>>(zlo, sp1);
    // cp1 = bn_relu(conv1x1(cp))
    conv1x1_kernel<<<dim3(NHW / 128, 1), 256>>>(cp, nullptr, CIN, CIN, 14, w_cp,
                                                gm_cp, b_cp, 1, cp1, C2);
    // redim = conv1x1(concat(cp1, sp1)) + b
    conv1x1_kernel<<<dim3(NHW / 128, 1), 256>>>(cp1, sp1, C2, 2 * C2, 14, w_redim,
                                                nullptr, b_redim, 0, redim, C2);
    simfdif_kernel<<<(NB * GR * HWD) / 256, 256>>>(cp1, sp1, fdif, sim);
    conv3x3_kernel<<<dim3(WW / 32, HH / 8, NB), 256>>>(sim, w_dir, b_dir, fdir, GR);
    conv3x3_kernel<<<dim3(WW / 32, HH / 8, NB), 256>>>(fdif, w_dist, b_dist, fdist, C2);
    offgrid_kernel<<<NHW / 32, 256>>>(redim, fdir, fdist, wofft, b_off, cp_t, spup_t, out);
}